// round 17
// baseline (speedup 1.0000x reference)
#include <cuda_runtime.h>
#include <cuda_fp16.h>
#include <cstdint>
#include <math.h>

#define BB  64
#define TT  128
#define INS 1024
#define HH  2048
#define NG  8192              // 4*H
#define MM  (BB*TT)           // 8192
#define BTH ((size_t)BB*(size_t)TT*(size_t)HH)   // 16,777,216

// ---------------- scratch (static device allocations only) ----------------
__device__ __half g_Xh[(size_t)MM*INS];            // x in fp16            16 MB
__device__ __half g_Wah[(size_t)128*64*HH];        // Wa reordered fp16    32 MB
__device__ __half g_Wxr[(size_t)128*64*INS];       // Wx reordered fp16    16 MB
__device__ __half g_Ah[2][(size_t)BB*HH];          // a_t ping-pong fp16
__device__ unsigned g_ctr;                         // grid-sync counter

// ---------------- helpers ----------------
__device__ __forceinline__ void cp_cg(uint32_t s, const void* g) {  // L1-bypass
    asm volatile("cp.async.cg.shared.global [%0], [%1], 16;" :: "r"(s), "l"(g));
}
#define CP_COMMIT() asm volatile("cp.async.commit_group;" ::: "memory")
#define CP_WAIT1()  asm volatile("cp.async.wait_group 1;"  ::: "memory")

__device__ __forceinline__ void ldsm4(uint32_t& r0, uint32_t& r1, uint32_t& r2, uint32_t& r3,
                                      uint32_t addr) {
    asm volatile("ldmatrix.sync.aligned.m8n8.x4.shared.b16 {%0,%1,%2,%3}, [%4];"
                 : "=r"(r0), "=r"(r1), "=r"(r2), "=r"(r3) : "r"(addr));
}

#define MMA16816(C0,C1,C2,C3,A0,A1,A2,A3,B0,B1)                                   \
    asm volatile("mma.sync.aligned.m16n8k16.row.col.f32.f16.f16.f32 "             \
                 "{%0,%1,%2,%3}, {%4,%5,%6,%7}, {%8,%9}, {%0,%1,%2,%3};"          \
                 : "+f"(C0), "+f"(C1), "+f"(C2), "+f"(C3)                         \
                 : "r"(A0), "r"(A1), "r"(A2), "r"(A3), "r"(B0), "r"(B1))

// ---------------- fused conversion kernel (1 launch) ----------------
__global__ void k_conv_all(const float* __restrict__ x, const float* __restrict__ wx,
                           const float* __restrict__ wa, const float* __restrict__ a0) {
    int i = blockIdx.x * blockDim.x + threadIdx.x;
    if (i == 0) g_ctr = 0;
    // Wa gather+convert: CTA j's 64 tile-cols {gate g, h=j*16+hh}, k-contiguous
    if (i < 128 * 64 * 1024) {
        int k2  = i & 1023;
        int rem = i >> 10;
        int n   = rem & 63;
        int j   = rem >> 6;
        int r   = (n >> 4) * HH + j * 16 + (n & 15);
        float2 v = *(const float2*)&wa[(size_t)r * HH + (size_t)k2 * 2];
        ((__half2*)g_Wah)[(size_t)(j * 64 + n) * 1024 + k2] = __floats2half2_rn(v.x, v.y);
    }
    // Wx gather+convert with the SAME tile-column ordering, K=INS=1024
    if (i < 128 * 64 * 512) {
        int k2  = i & 511;
        int rem = i >> 9;
        int n   = rem & 63;
        int j   = rem >> 6;
        int r   = (n >> 4) * HH + j * 16 + (n & 15);
        float2 v = *(const float2*)&wx[(size_t)r * INS + (size_t)k2 * 2];
        ((__half2*)g_Wxr)[(size_t)(j * 64 + n) * 512 + k2] = __floats2half2_rn(v.x, v.y);
    }
    if (i < MM * INS / 2) {
        float2 v = ((const float2*)x)[i];
        ((__half2*)g_Xh)[i] = __floats2half2_rn(v.x, v.y);
    }
    if (i < BB * HH / 2) {
        float2 v = ((const float2*)a0)[i];
        ((__half2*)g_Ah[0])[i] = __floats2half2_rn(v.x, v.y);
    }
}

// ============================================================================
// fused persistent LSTM kernel — x-GEMM folded into the recurrence.
// 128 CTAs, 256 threads (8 warps, 2x4, warp tile 32x16), CTA j owns h-slice 16.
// Per step: Phase X (4 K-chunks of x_t @ Wxr^T, NO sync dependency — overlaps
// the grid-sync skew), then sync-wait, then Phase A (8 K-chunks of a@Wa^T),
// all into the same f32 accumulators. Bias folded in registers.
// ============================================================================
#define KC2  256                                 // K-chunk (halves)
#define LD2  264                                 // halves; 528B stride (=16 mod 128)
#define L_STG (2 * 64 * LD2)                     // halves per stage (A+B) = 33792
#define LSTM_SMEM (3 * L_STG * 2 + 64 * 66 * 4)  // 202752 + 16896 = 219648 B

__global__ __launch_bounds__(256) void k_lstm(const float* __restrict__ bias,
                                              const float* __restrict__ c0,
                                              float* __restrict__ out) {
    extern __shared__ __half sm[];
    uint32_t smb = (uint32_t)__cvta_generic_to_shared(sm);
    float* yt = (float*)(sm + 3 * L_STG);

    int tid = threadIdx.x, lane = tid & 31, wid = tid >> 5;
    int wm = wid >> 2, wn = wid & 3;                 // 2x4 warps, warp tile 32x16
    int gq = lane >> 2, tq = lane & 3;
    int j = blockIdx.x;
    int h0 = j * 16;

    int aro = lane & 15;
    int ako = (lane >> 4) * 8;

    int hh = tid & 15, mb = tid >> 4;                // epilogue: 4 (m,hh) pairs/thread
    float cprev[4];
#pragma unroll
    for (int p = 0; p < 4; p++)
        cprev[p] = c0[(size_t)(p * 16 + mb) * HH + h0 + hh];

    // bias for this thread's 4 gate columns
    float brg[4];
#pragma unroll
    for (int g = 0; g < 4; g++)
        brg[g] = bias[g * HH + h0 + hh];

    const __half* Wp  = g_Wah + (size_t)j * 64 * HH;    // recurrent weights
    const __half* Wxp = g_Wxr + (size_t)j * 64 * INS;   // input weights

    // Phase-A loader: A = a_{t-1} rows (stride HH), B = Wa rows (stride HH)
#define LA_LOAD(st, k0)                                                            \
    {                                                                              \
        uint32_t sa = smb + (uint32_t)(st) * (L_STG * 2);                          \
        uint32_t sb = sa + 64 * LD2 * 2;                                           \
        _Pragma("unroll")                                                          \
        for (int q = 0; q < 8; q++) {                                              \
            int s = tid + q * 256;                                                 \
            int row = s >> 5, c = s & 31;                                          \
            uint32_t off = (uint32_t)(row * LD2 + c * 8) * 2;                      \
            cp_cg(sa + off, Ard + (size_t)row * HH + (k0) + c * 8);                \
            cp_cg(sb + off, Wp + (size_t)row * HH + (k0) + c * 8);                 \
        }                                                                          \
    }
    // Phase-X loader: A = x_t rows (row stride TT*INS), B = Wxr rows (stride INS)
#define LX_LOAD(st, k0)                                                            \
    {                                                                              \
        uint32_t sa = smb + (uint32_t)(st) * (L_STG * 2);                          \
        uint32_t sb = sa + 64 * LD2 * 2;                                           \
        _Pragma("unroll")                                                          \
        for (int q = 0; q < 8; q++) {                                              \
            int s = tid + q * 256;                                                 \
            int row = s >> 5, c = s & 31;                                          \
            uint32_t off = (uint32_t)(row * LD2 + c * 8) * 2;                      \
            cp_cg(sa + off, Xt + (size_t)row * (TT * INS) + (k0) + c * 8);         \
            cp_cg(sb + off, Wxp + (size_t)row * INS + (k0) + c * 8);               \
        }                                                                          \
    }
    // MMA over one staged chunk (identical layout for both phases)
#define CHUNK_MMA(stg)                                                             \
    {                                                                              \
        uint32_t sA = smb + (uint32_t)(stg) * (L_STG * 2);                         \
        uint32_t aBase = sA + (uint32_t)((wm * 32 + aro) * LD2 + ako) * 2;         \
        const __half* Bsp = sm + (size_t)(stg) * L_STG + 64 * LD2;                 \
        _Pragma("unroll")                                                          \
        for (int kb = 0; kb < KC2; kb += 16) {                                     \
            int s2 = (kb >> 4) & 1;                                                \
            uint32_t af[2][4], bf[2][2];                                           \
            _Pragma("unroll")                                                      \
            for (int mt = 0; mt < 2; mt++)                                         \
                ldsm4(af[mt][0], af[mt][1], af[mt][2], af[mt][3],                  \
                      aBase + (uint32_t)(mt * 16 * LD2 + kb) * 2);                 \
            _Pragma("unroll")                                                      \
            for (int nt = 0; nt < 2; nt++) {                                       \
                int cc = wn * 16 + nt * 8;                                         \
                bf[nt][0] = *(const uint32_t*)&Bsp[(cc + gq) * LD2 + kb + 2 * tq]; \
                bf[nt][1] = *(const uint32_t*)&Bsp[(cc + gq) * LD2 + kb + 2 * tq + 8]; \
            }                                                                      \
            _Pragma("unroll")                                                      \
            for (int mt = 0; mt < 2; mt++)                                         \
                _Pragma("unroll")                                                  \
                for (int nt = 0; nt < 2; nt++)                                     \
                    MMA16816(acc[s2][mt][nt][0], acc[s2][mt][nt][1],               \
                             acc[s2][mt][nt][2], acc[s2][mt][nt][3],               \
                             af[mt][0], af[mt][1], af[mt][2], af[mt][3],           \
                             bf[nt][0], bf[nt][1]);                                \
        }                                                                          \
    }

    for (int t = 0; t < TT; t++) {
        const __half* Ard = g_Ah[t & 1];
        __half*       Awr = g_Ah[(t + 1) & 1];
        const __half* Xt  = g_Xh + (size_t)t * INS;

        // two accumulator sets (ping-pong over kb) -> 8 independent chains/warp
        float acc[2][2][2][4];
#pragma unroll
        for (int s2 = 0; s2 < 2; s2++)
#pragma unroll
            for (int a = 0; a < 2; a++)
#pragma unroll
                for (int b = 0; b < 2; b++)
#pragma unroll
                    for (int q = 0; q < 4; q++) acc[s2][a][b][q] = 0.f;

        // ---- Phase X: y += x_t @ Wxr^T  (independent of grid sync) ----
        LX_LOAD(0, 0);    CP_COMMIT();
        LX_LOAD(1, KC2);  CP_COMMIT();
        for (int it = 0; it < 4; it++) {
            CP_WAIT1();
            __syncthreads();
            int nk = it + 2;
            if (nk < 4) LX_LOAD(nk % 3, nk * KC2);
            CP_COMMIT();
            CHUNK_MMA(it % 3);
        }

        // ---- grid-sync wait: a_{t-1} from all CTAs must be visible ----
        if (t > 0) {
            if (tid == 0) {
                unsigned tgt = (unsigned)t * (unsigned)gridDim.x;
                unsigned v;
                do {
                    asm volatile("ld.global.cg.u32 %0, [%1];" : "=r"(v) : "l"(&g_ctr) : "memory");
                    if (v < tgt) __nanosleep(32);
                } while (v < tgt);
                __threadfence();
            }
            __syncthreads();
        }

        // ---- Phase A: y += a_{t-1} @ Wa^T ----
        LA_LOAD(0, 0);    CP_COMMIT();
        LA_LOAD(1, KC2);  CP_COMMIT();
        for (int it = 0; it < 8; it++) {
            CP_WAIT1();
            __syncthreads();
            int nk = it + 2;
            if (nk < 8) LA_LOAD(nk % 3, nk * KC2);
            CP_COMMIT();
            CHUNK_MMA(it % 3);
        }

        // stage gate pre-activations (sum of both acc sets) into smem
#pragma unroll
        for (int mt = 0; mt < 2; mt++) {
#pragma unroll
            for (int nt = 0; nt < 2; nt++) {
                int r = wm * 32 + mt * 16 + gq;
                int cc = wn * 16 + nt * 8 + 2 * tq;
                yt[r * 66 + cc]           = acc[0][mt][nt][0] + acc[1][mt][nt][0];
                yt[r * 66 + cc + 1]       = acc[0][mt][nt][1] + acc[1][mt][nt][1];
                yt[(r + 8) * 66 + cc]     = acc[0][mt][nt][2] + acc[1][mt][nt][2];
                yt[(r + 8) * 66 + cc + 1] = acc[0][mt][nt][3] + acc[1][mt][nt][3];
            }
        }
        __syncthreads();

        // elementwise LSTM epilogue (bias in registers; c_t register-resident)
#pragma unroll
        for (int p = 0; p < 4; p++) {
            int m = p * 16 + mb;                     // batch index
            size_t bofs = ((size_t)m * TT + t) * HH + h0 + hh;
            float yi = yt[m * 66 + hh]      + brg[0];
            float yf = yt[m * 66 + 16 + hh] + brg[1];
            float yg = yt[m * 66 + 32 + hh] + brg[2];
            float yo = yt[m * 66 + 48 + hh] + brg[3];
            float si = 1.f / (1.f + expf(-yi));
            float sf = 1.f / (1.f + expf(-yf));
            float so = 1.f / (1.f + expf(-yo));
            float cn = sf * cprev[p] + si * tanhf(yg);
            float an = so * tanhf(cn);
            cprev[p] = cn;
            __stcs(out + 2 * BTH + bofs, yi);
            __stcs(out + 3 * BTH + bofs, yf);
            __stcs(out + 4 * BTH + bofs, yg);
            __stcs(out + 5 * BTH + bofs, yo);
            __stcs(out + bofs, an);
            __stcs(out + BTH + bofs, cn);
            Awr[(size_t)m * HH + h0 + hh] = __float2half_rn(an);
        }

        // arrive (wait happens at the top of the next step, after Phase X)
        if (t < TT - 1) {
            __threadfence();                         // release a_t writes
            __syncthreads();
            if (tid == 0) atomicAdd(&g_ctr, 1u);
        }
    }
}

// ---------------- launch ----------------
extern "C" void kernel_launch(void* const* d_in, const int* in_sizes, int n_in,
                              void* d_out, int out_size) {
    (void)in_sizes; (void)n_in; (void)out_size;
    const float* x  = (const float*)d_in[0];
    const float* Wx = (const float*)d_in[1];
    const float* Wa = (const float*)d_in[2];
    const float* b  = (const float*)d_in[3];
    const float* a0 = (const float*)d_in[4];
    const float* c0 = (const float*)d_in[5];
    float* out = (float*)d_out;

    cudaFuncSetAttribute(k_lstm, cudaFuncAttributeMaxDynamicSharedMemorySize, LSTM_SMEM);

    int nconv = 128 * 64 * 1024;                 // largest section (Wa half2 count)
    k_conv_all<<<(nconv + 255) / 256, 256>>>(x, Wx, Wa, a0);
    k_lstm<<<128, 256, LSTM_SMEM>>>(b, c0, out);
}